// round 8
// baseline (speedup 1.0000x reference)
#include <cuda_runtime.h>

#define NN 100000
#define NE 3200000
#define BKT 128          // fixed bucket capacity per node (Poisson(32) — safe)

// ---------------- scratch (device-only references) --------------------------
__device__ int g_cnt[NN];
__device__ int g_bkt[NN * BKT];          // 51.2 MB bucketed adjacency
__device__ __align__(16) float g_p [NN * 32];   // projection buffer (reused)
__device__ __align__(16) float g_d1[NN * 32];   // layer-1 out (dropout, pre-scaled)
__device__ __align__(16) float g_d2[NN * 64];   // layer-2 out (post dropout)

template<int ID> __device__ __forceinline__ float* bufptr();
template<> __device__ __forceinline__ float* bufptr<0>() { return g_p;  }
template<> __device__ __forceinline__ float* bufptr<1>() { return g_d1; }
template<> __device__ __forceinline__ float* bufptr<2>() { return g_d2; }

// ---------------- JAX threefry2x32 ------------------------------------------
struct U2 { unsigned x, y; };

__host__ __device__ constexpr unsigned rotl32(unsigned v, int r) {
  return (v << r) | (v >> (32 - r));
}

__host__ __device__ constexpr U2 threefry2x32(unsigned k0, unsigned k1,
                                              unsigned c0, unsigned c1) {
  unsigned ks2 = k0 ^ k1 ^ 0x1BD11BDAu;
  unsigned x0 = c0 + k0;
  unsigned x1 = c1 + k1;
  x0 += x1; x1 = rotl32(x1, 13); x1 ^= x0;
  x0 += x1; x1 = rotl32(x1, 15); x1 ^= x0;
  x0 += x1; x1 = rotl32(x1, 26); x1 ^= x0;
  x0 += x1; x1 = rotl32(x1,  6); x1 ^= x0;
  x0 += k1;  x1 += ks2 + 1u;
  x0 += x1; x1 = rotl32(x1, 17); x1 ^= x0;
  x0 += x1; x1 = rotl32(x1, 29); x1 ^= x0;
  x0 += x1; x1 = rotl32(x1, 16); x1 ^= x0;
  x0 += x1; x1 = rotl32(x1, 24); x1 ^= x0;
  x0 += ks2; x1 += k0 + 2u;
  x0 += x1; x1 = rotl32(x1, 13); x1 ^= x0;
  x0 += x1; x1 = rotl32(x1, 15); x1 ^= x0;
  x0 += x1; x1 = rotl32(x1, 26); x1 ^= x0;
  x0 += x1; x1 = rotl32(x1,  6); x1 ^= x0;
  x0 += k0;  x1 += k1 + 3u;
  x0 += x1; x1 = rotl32(x1, 17); x1 ^= x0;
  x0 += x1; x1 = rotl32(x1, 29); x1 ^= x0;
  x0 += x1; x1 = rotl32(x1, 16); x1 ^= x0;
  x0 += x1; x1 = rotl32(x1, 24); x1 ^= x0;
  x0 += k1;  x1 += ks2 + 4u;
  x0 += x1; x1 = rotl32(x1, 13); x1 ^= x0;
  x0 += x1; x1 = rotl32(x1, 15); x1 ^= x0;
  x0 += x1; x1 = rotl32(x1, 26); x1 ^= x0;
  x0 += x1; x1 = rotl32(x1,  6); x1 ^= x0;
  x0 += ks2; x1 += k0 + 5u;
  return U2{x0, x1};
}

constexpr U2 DKEY1 = threefry2x32(0u, 42u, 0u, 0u);
constexpr U2 DKEY2 = threefry2x32(0u, 42u, 0u, 1u);

__device__ __forceinline__ float jax_dropout(float v, unsigned ka, unsigned kb,
                                             unsigned idx) {
  U2 r = threefry2x32(ka, kb, 0u, idx);
  return ((r.x ^ r.y) & 0x80000000u) ? 0.0f : v * 2.0f;
}

__device__ __forceinline__ float celu1(float v) {
  return v > 0.0f ? v : expm1f(v);
}

// ---------------- graph preprocessing (edge_index is int32) -----------------
__global__ void zero_cnt_kernel() {
  int i = blockIdx.x * blockDim.x + threadIdx.x;
  if (i < NN) g_cnt[i] = 0;
}

// One pass: counter doubles as bucket cursor. 8 edges/thread for MLP.
__global__ void fill_kernel(const int* __restrict__ ei) {
  int t = blockIdx.x * blockDim.x + threadIdx.x;
  if (t >= NE / 8) return;
  int4 sa = reinterpret_cast<const int4*>(ei)[t * 2];
  int4 sb = reinterpret_cast<const int4*>(ei)[t * 2 + 1];
  int4 da = reinterpret_cast<const int4*>(ei + NE)[t * 2];
  int4 db = reinterpret_cast<const int4*>(ei + NE)[t * 2 + 1];
  int ss[8] = {sa.x, sa.y, sa.z, sa.w, sb.x, sb.y, sb.z, sb.w};
  int dd[8] = {da.x, da.y, da.z, da.w, db.x, db.y, db.z, db.w};
  #pragma unroll
  for (int u = 0; u < 8; ++u) {
    int d = dd[u];
    if ((unsigned)d < (unsigned)NN) {
      int p = atomicAdd(&g_cnt[d], 1);
      if (p < BKT) g_bkt[d * BKT + p] = ss[u];
    }
  }
}

// ---------------- dense projection: out = in @ W (+epilogue) ----------------
// SCALE: multiply output row by dinv[n] = rsqrt(deg+1), computed from g_cnt.
template<int FIN, int FOUT, int POST, int SCALE, int SRC, int DST>
__global__ void __launch_bounds__(256)
proj_kernel(const float* __restrict__ xin, const float* __restrict__ W,
            const float* __restrict__ bias, unsigned ka, unsigned kb) {
  __shared__ __align__(16) float sW[FIN * FOUT];
  for (int i = threadIdx.x; i < FIN * FOUT; i += 256) sW[i] = W[i];
  __syncthreads();

  const float* in = (SRC < 0) ? xin : bufptr<(SRC < 0) ? 0 : SRC>();
  float* out = bufptr<DST>();

  constexpr int TPN = FOUT / 4;
  int gid = blockIdx.x * blockDim.x + threadIdx.x;
  int n  = gid / TPN;
  int f4 = (gid % TPN) * 4;
  if (n >= NN) return;

  const float4* xrow = reinterpret_cast<const float4*>(in + (size_t)n * FIN);
  float a0 = 0.f, a1 = 0.f, a2 = 0.f, a3 = 0.f;
  #pragma unroll
  for (int k4 = 0; k4 < FIN / 4; ++k4) {
    float4 xv = xrow[k4];
    #pragma unroll
    for (int r = 0; r < 4; ++r) {
      float xs = (r == 0) ? xv.x : (r == 1) ? xv.y : (r == 2) ? xv.z : xv.w;
      float4 wv = *reinterpret_cast<const float4*>(&sW[(k4 * 4 + r) * FOUT + f4]);
      a0 += xs * wv.x; a1 += xs * wv.y; a2 += xs * wv.z; a3 += xs * wv.w;
    }
  }
  int ob = n * FOUT + f4;
  float vv[4] = {a0, a1, a2, a3};
  if (POST == 1) {
    #pragma unroll
    for (int r = 0; r < 4; ++r) {
      float v = vv[r] + bias[f4 + r];
      v = celu1(v);
      vv[r] = jax_dropout(v, ka, kb, (unsigned)(ob + r));
    }
  }
  if (SCALE) {
    float dn = rsqrtf((float)(g_cnt[n] + 1));
    #pragma unroll
    for (int r = 0; r < 4; ++r) vv[r] *= dn;
  }
  *reinterpret_cast<float4*>(out + ob) = make_float4(vv[0], vv[1], vv[2], vv[3]);
}

// ---------------- aggregation (pair-gather, packed f32x2), warp per node ----
// p holds dinv[i]*row_i. Lane split: eslot = lane>>4 (which of 2 edges per
// step), k = lane&15 (feature pair). Each step: 2 edges gathered, each lane
// one float2 + one add.rn.f32x2. End: xor-16 reduce + redistribute to
// one-feature-per-lane for the (unchanged) epilogue.
template<int POST, int OUTSCALE, int SRC, int DST>
__global__ void __launch_bounds__(256)
agg_kernel(const float* __restrict__ bias, float* __restrict__ xout,
           unsigned ka, unsigned kb) {
  const float* p = bufptr<SRC>();
  float* out = (DST < 0) ? xout : bufptr<(DST < 0) ? 0 : DST>();

  int gid  = blockIdx.x * blockDim.x + threadIdx.x;
  int j    = gid >> 5;
  int lane = gid & 31;
  if (j >= NN) return;

  int eslot = lane >> 4;     // 0 or 1
  int k     = lane & 15;     // feature-pair index
  int deg = g_cnt[j];
  int bbase = j * BKT;
  float dj = rsqrtf((float)(deg + 1));

  const char* pk = reinterpret_cast<const char*>(p) + (k << 3);

  unsigned long long acc64 = 0ull;   // packed float2 accumulator
  if (eslot == 0)   // self loop (pre-scaled row), counted once
    acc64 = __ldg(reinterpret_cast<const unsigned long long*>(pk + (size_t)j * 128));

  int e = 0;
  while (e + 32 <= deg) {
    int idxv = __ldg(&g_bkt[bbase + e + lane]);
    #pragma unroll
    for (int st = 0; st < 16; ++st) {
      int i = __shfl_sync(0xffffffffu, idxv, st * 2 + eslot);
      unsigned long long v64 =
          __ldg(reinterpret_cast<const unsigned long long*>(pk + (size_t)i * 128));
      asm("add.rn.f32x2 %0, %0, %1;" : "+l"(acc64) : "l"(v64));
    }
    e += 32;
  }
  int rem = deg - e;
  if (rem > 0) {
    int idxv = (lane < rem) ? __ldg(&g_bkt[bbase + e + lane]) : 0;
    #pragma unroll
    for (int st = 0; st < 16; ++st) {
      int t = st * 2 + eslot;
      int i = __shfl_sync(0xffffffffu, idxv, t);
      if (t < rem) {
        unsigned long long v64 =
            __ldg(reinterpret_cast<const unsigned long long*>(pk + (size_t)i * 128));
        asm("add.rn.f32x2 %0, %0, %1;" : "+l"(acc64) : "l"(v64));
      }
    }
  }

  // unpack, reduce the two eslot halves (lanes l and l+16 share k)
  float ax, ay;
  asm("mov.b64 {%0, %1}, %2;" : "=f"(ax), "=f"(ay) : "l"(acc64));
  ax += __shfl_xor_sync(0xffffffffu, ax, 16);
  ay += __shfl_xor_sync(0xffffffffu, ay, 16);

  // redistribute: feature f=lane lives in pair (lane>>1) held by that lane
  float vx = __shfl_sync(0xffffffffu, ax, lane >> 1);
  float vy = __shfl_sync(0xffffffffu, ay, lane >> 1);
  float v = (lane & 1) ? vy : vx;

  v *= dj;
  if (POST >= 1) {
    v += bias[lane];
    v = celu1(v);
  }
  if (POST == 1) {
    v = jax_dropout(v, ka, kb, (unsigned)(j * 32 + lane));
  }
  if (OUTSCALE) v *= dj;
  out[j * 32 + lane] = v;
}

// ---------------- launch -----------------------------------------------------
extern "C" void kernel_launch(void* const* d_in, const int* in_sizes, int n_in,
                              void* d_out, int out_size) {
  const float* x  = (const float*)d_in[0];
  const int*   ei = (const int*)d_in[1];      // int32 (JAX x64 disabled)
  const float* W1 = (const float*)d_in[2];
  const float* b1 = (const float*)d_in[3];
  const float* W2 = (const float*)d_in[4];
  const float* b2 = (const float*)d_in[5];
  const float* W3 = (const float*)d_in[6];
  const float* b3 = (const float*)d_in[7];
  float* out = (float*)d_out;

  const int E8 = (NE / 8 + 255) / 256;    // 1563
  const int WB = (NN * 32 + 255) / 256;   // 12500 (warp-per-node)

  // One-pass bucketed adjacency build
  zero_cnt_kernel<<<(NN + 255) / 256, 256>>>();                       // 1
  fill_kernel<<<E8, 256>>>(ei);                                       // 2

  // Layer 1: g_p = dinv .* (x@W1) ; g_d1 = dinv .* dropout(celu(dj*Σ + b1))
  proj_kernel<64, 32, 0, 1, -1, 0><<<(NN * 8 + 255) / 256, 256>>>(x, W1, nullptr, 0u, 0u);  // 3
  agg_kernel<1, 1, 0, 1><<<WB, 256>>>(b1, nullptr, DKEY1.x, DKEY1.y); // 4 (profiled)

  // Layer 2: g_p = dj*Σ(g_d1) ; g_d2 = dropout(celu(g_p@W2 + b2))
  agg_kernel<0, 0, 1, 0><<<WB, 256>>>(nullptr, nullptr, 0u, 0u);      // 5
  proj_kernel<32, 64, 1, 0, 0, 2><<<(NN * 16 + 255) / 256, 256>>>(nullptr, W2, b2,
                                                                  DKEY2.x, DKEY2.y);  // 6

  // Layer 3: g_p = dinv .* (g_d2@W3) ; out = celu(dj*Σ + b3)
  proj_kernel<64, 32, 0, 1, 2, 0><<<(NN * 8 + 255) / 256, 256>>>(nullptr, W3, nullptr, 0u, 0u);  // 7
  agg_kernel<2, 0, 0, -1><<<WB, 256>>>(b3, out, 0u, 0u);              // 8
}

// round 9
// speedup vs baseline: 1.0562x; 1.0562x over previous
#include <cuda_runtime.h>

#define NN 100000
#define NE 3200000
#define BKT 128          // fixed bucket capacity per node (Poisson(32) — safe)

// ---------------- scratch (device-only references) --------------------------
__device__ int g_cnt[NN];
__device__ int g_bkt[NN * BKT];          // 51.2 MB bucketed adjacency
__device__ __align__(16) float g_p [NN * 32];   // projection buffer (reused)
__device__ __align__(16) float g_d1[NN * 32];   // layer-1 out (dropout, pre-scaled)
__device__ __align__(16) float g_d2[NN * 64];   // layer-2 out (post dropout)

template<int ID> __device__ __forceinline__ float* bufptr();
template<> __device__ __forceinline__ float* bufptr<0>() { return g_p;  }
template<> __device__ __forceinline__ float* bufptr<1>() { return g_d1; }
template<> __device__ __forceinline__ float* bufptr<2>() { return g_d2; }

// ---------------- JAX threefry2x32 ------------------------------------------
struct U2 { unsigned x, y; };

__host__ __device__ constexpr unsigned rotl32(unsigned v, int r) {
  return (v << r) | (v >> (32 - r));
}

__host__ __device__ constexpr U2 threefry2x32(unsigned k0, unsigned k1,
                                              unsigned c0, unsigned c1) {
  unsigned ks2 = k0 ^ k1 ^ 0x1BD11BDAu;
  unsigned x0 = c0 + k0;
  unsigned x1 = c1 + k1;
  x0 += x1; x1 = rotl32(x1, 13); x1 ^= x0;
  x0 += x1; x1 = rotl32(x1, 15); x1 ^= x0;
  x0 += x1; x1 = rotl32(x1, 26); x1 ^= x0;
  x0 += x1; x1 = rotl32(x1,  6); x1 ^= x0;
  x0 += k1;  x1 += ks2 + 1u;
  x0 += x1; x1 = rotl32(x1, 17); x1 ^= x0;
  x0 += x1; x1 = rotl32(x1, 29); x1 ^= x0;
  x0 += x1; x1 = rotl32(x1, 16); x1 ^= x0;
  x0 += x1; x1 = rotl32(x1, 24); x1 ^= x0;
  x0 += ks2; x1 += k0 + 2u;
  x0 += x1; x1 = rotl32(x1, 13); x1 ^= x0;
  x0 += x1; x1 = rotl32(x1, 15); x1 ^= x0;
  x0 += x1; x1 = rotl32(x1, 26); x1 ^= x0;
  x0 += x1; x1 = rotl32(x1,  6); x1 ^= x0;
  x0 += k0;  x1 += k1 + 3u;
  x0 += x1; x1 = rotl32(x1, 17); x1 ^= x0;
  x0 += x1; x1 = rotl32(x1, 29); x1 ^= x0;
  x0 += x1; x1 = rotl32(x1, 16); x1 ^= x0;
  x0 += x1; x1 = rotl32(x1, 24); x1 ^= x0;
  x0 += k1;  x1 += ks2 + 4u;
  x0 += x1; x1 = rotl32(x1, 13); x1 ^= x0;
  x0 += x1; x1 = rotl32(x1, 15); x1 ^= x0;
  x0 += x1; x1 = rotl32(x1, 26); x1 ^= x0;
  x0 += x1; x1 = rotl32(x1,  6); x1 ^= x0;
  x0 += ks2; x1 += k0 + 5u;
  return U2{x0, x1};
}

constexpr U2 DKEY1 = threefry2x32(0u, 42u, 0u, 0u);
constexpr U2 DKEY2 = threefry2x32(0u, 42u, 0u, 1u);

__device__ __forceinline__ float jax_dropout(float v, unsigned ka, unsigned kb,
                                             unsigned idx) {
  U2 r = threefry2x32(ka, kb, 0u, idx);
  return ((r.x ^ r.y) & 0x80000000u) ? 0.0f : v * 2.0f;
}

__device__ __forceinline__ float celu1(float v) {
  return v > 0.0f ? v : expm1f(v);
}

// ---------------- graph preprocessing (edge_index is int32) -----------------
__global__ void zero_cnt_kernel() {
  int i = blockIdx.x * blockDim.x + threadIdx.x;
  if (i < NN) g_cnt[i] = 0;
}

// One pass: counter doubles as bucket cursor (4 edges/thread — best measured).
__global__ void fill_kernel(const int* __restrict__ ei) {
  int t = blockIdx.x * blockDim.x + threadIdx.x;
  if (t >= NE / 4) return;
  int4 s4 = reinterpret_cast<const int4*>(ei)[t];
  int4 d4 = reinterpret_cast<const int4*>(ei + NE)[t];
  if ((unsigned)d4.x < (unsigned)NN) {
    int p = atomicAdd(&g_cnt[d4.x], 1);
    if (p < BKT) g_bkt[d4.x * BKT + p] = s4.x;
  }
  if ((unsigned)d4.y < (unsigned)NN) {
    int p = atomicAdd(&g_cnt[d4.y], 1);
    if (p < BKT) g_bkt[d4.y * BKT + p] = s4.y;
  }
  if ((unsigned)d4.z < (unsigned)NN) {
    int p = atomicAdd(&g_cnt[d4.z], 1);
    if (p < BKT) g_bkt[d4.z * BKT + p] = s4.z;
  }
  if ((unsigned)d4.w < (unsigned)NN) {
    int p = atomicAdd(&g_cnt[d4.w], 1);
    if (p < BKT) g_bkt[d4.w * BKT + p] = s4.w;
  }
}

// ---------------- dense projection: out = in @ W (+epilogue) ----------------
// SCALE: multiply output row by dinv[n] = rsqrt(deg+1), computed from g_cnt.
template<int FIN, int FOUT, int POST, int SCALE, int SRC, int DST>
__global__ void __launch_bounds__(256)
proj_kernel(const float* __restrict__ xin, const float* __restrict__ W,
            const float* __restrict__ bias, unsigned ka, unsigned kb) {
  __shared__ __align__(16) float sW[FIN * FOUT];
  for (int i = threadIdx.x; i < FIN * FOUT; i += 256) sW[i] = W[i];
  __syncthreads();

  const float* in = (SRC < 0) ? xin : bufptr<(SRC < 0) ? 0 : SRC>();
  float* out = bufptr<DST>();

  constexpr int TPN = FOUT / 4;
  int gid = blockIdx.x * blockDim.x + threadIdx.x;
  int n  = gid / TPN;
  int f4 = (gid % TPN) * 4;
  if (n >= NN) return;

  const float4* xrow = reinterpret_cast<const float4*>(in + (size_t)n * FIN);
  float a0 = 0.f, a1 = 0.f, a2 = 0.f, a3 = 0.f;
  #pragma unroll
  for (int k4 = 0; k4 < FIN / 4; ++k4) {
    float4 xv = xrow[k4];
    #pragma unroll
    for (int r = 0; r < 4; ++r) {
      float xs = (r == 0) ? xv.x : (r == 1) ? xv.y : (r == 2) ? xv.z : xv.w;
      float4 wv = *reinterpret_cast<const float4*>(&sW[(k4 * 4 + r) * FOUT + f4]);
      a0 += xs * wv.x; a1 += xs * wv.y; a2 += xs * wv.z; a3 += xs * wv.w;
    }
  }
  int ob = n * FOUT + f4;
  float vv[4] = {a0, a1, a2, a3};
  if (POST == 1) {
    #pragma unroll
    for (int r = 0; r < 4; ++r) {
      float v = vv[r] + bias[f4 + r];
      v = celu1(v);
      vv[r] = jax_dropout(v, ka, kb, (unsigned)(ob + r));
    }
  }
  if (SCALE) {
    float dn = rsqrtf((float)(g_cnt[n] + 1));
    #pragma unroll
    for (int r = 0; r < 4; ++r) vv[r] *= dn;
  }
  *reinterpret_cast<float4*>(out + ob) = make_float4(vv[0], vv[1], vv[2], vv[3]);
}

// ---------------- aggregation (float4 gather + packed f32x2 adds) -----------
// One warp per node. Quad q = lane>>3 handles edge (step*4+q); sub s = lane&7
// handles features [4s,4s+4) loaded as ulonglong2 (LDG.128), accumulated with
// two add.rn.f32x2 (same rounding/order as 4 FADDs). Quad sums reduced +
// redistributed to one-feature-per-lane for the epilogue.
template<int POST, int OUTSCALE, int SRC, int DST>
__global__ void __launch_bounds__(256)
agg_kernel(const float* __restrict__ bias, float* __restrict__ xout,
           unsigned ka, unsigned kb) {
  const float* p = bufptr<SRC>();
  float* out = (DST < 0) ? xout : bufptr<(DST < 0) ? 0 : DST>();

  int gid  = blockIdx.x * blockDim.x + threadIdx.x;
  int j    = gid >> 5;
  int lane = gid & 31;
  if (j >= NN) return;

  int q = lane >> 3;
  int s = lane & 7;
  int deg = g_cnt[j];
  int beg = j * BKT;
  int end = beg + deg;
  float dj = rsqrtf((float)(deg + 1));

  unsigned long long a01 = 0ull, a23 = 0ull;   // packed f32x2 accumulators
  if (q == 0) {   // self loop (pre-scaled row), counted once
    ulonglong2 sv = __ldg(reinterpret_cast<const ulonglong2*>(&p[j * 32 + s * 4]));
    a01 = sv.x; a23 = sv.y;
  }

  int e = beg;
  while (e + 32 <= end) {
    int idxv = __ldg(&g_bkt[e + lane]);
    #pragma unroll
    for (int k = 0; k < 8; ++k) {
      int i = __shfl_sync(0xffffffffu, idxv, k * 4 + q);
      ulonglong2 v = __ldg(reinterpret_cast<const ulonglong2*>(&p[i * 32 + s * 4]));
      asm("add.rn.f32x2 %0, %0, %1;" : "+l"(a01) : "l"(v.x));
      asm("add.rn.f32x2 %0, %0, %1;" : "+l"(a23) : "l"(v.y));
    }
    e += 32;
  }
  int rem = end - e;
  if (rem > 0) {
    int idxv = (lane < rem) ? __ldg(&g_bkt[e + lane]) : 0;
    #pragma unroll
    for (int k = 0; k < 8; ++k) {
      int t = k * 4 + q;
      int i = __shfl_sync(0xffffffffu, idxv, t);
      if (t < rem) {
        ulonglong2 v = __ldg(reinterpret_cast<const ulonglong2*>(&p[i * 32 + s * 4]));
        asm("add.rn.f32x2 %0, %0, %1;" : "+l"(a01) : "l"(v.x));
        asm("add.rn.f32x2 %0, %0, %1;" : "+l"(a23) : "l"(v.y));
      }
    }
  }

  // unpack to 4 floats (same layout as R7's float4 acc)
  float ax, ay, az, aw;
  asm("mov.b64 {%0, %1}, %2;" : "=f"(ax), "=f"(ay) : "l"(a01));
  asm("mov.b64 {%0, %1}, %2;" : "=f"(az), "=f"(aw) : "l"(a23));

  // reduce across the 4 quads (lanes sharing s)
  #pragma unroll
  for (int d = 8; d < 32; d <<= 1) {
    ax += __shfl_xor_sync(0xffffffffu, ax, d);
    ay += __shfl_xor_sync(0xffffffffu, ay, d);
    az += __shfl_xor_sync(0xffffffffu, az, d);
    aw += __shfl_xor_sync(0xffffffffu, aw, d);
  }
  // redistribute: lane wants feature 'lane' = component (lane&3) of chunk lane>>2
  int srcl = lane >> 2;
  float v0 = __shfl_sync(0xffffffffu, ax, srcl);
  float v1 = __shfl_sync(0xffffffffu, ay, srcl);
  float v2 = __shfl_sync(0xffffffffu, az, srcl);
  float v3 = __shfl_sync(0xffffffffu, aw, srcl);
  int r = lane & 3;
  float v = (r == 0) ? v0 : (r == 1) ? v1 : (r == 2) ? v2 : v3;

  v *= dj;
  if (POST >= 1) {
    v += bias[lane];
    v = celu1(v);
  }
  if (POST == 1) {
    v = jax_dropout(v, ka, kb, (unsigned)(j * 32 + lane));
  }
  if (OUTSCALE) v *= dj;
  out[j * 32 + lane] = v;
}

// ---------------- launch -----------------------------------------------------
extern "C" void kernel_launch(void* const* d_in, const int* in_sizes, int n_in,
                              void* d_out, int out_size) {
  const float* x  = (const float*)d_in[0];
  const int*   ei = (const int*)d_in[1];      // int32 (JAX x64 disabled)
  const float* W1 = (const float*)d_in[2];
  const float* b1 = (const float*)d_in[3];
  const float* W2 = (const float*)d_in[4];
  const float* b2 = (const float*)d_in[5];
  const float* W3 = (const float*)d_in[6];
  const float* b3 = (const float*)d_in[7];
  float* out = (float*)d_out;

  const int E4 = (NE / 4 + 255) / 256;    // 3125
  const int WB = (NN * 32 + 255) / 256;   // 12500 (warp-per-node)

  // One-pass bucketed adjacency build
  zero_cnt_kernel<<<(NN + 255) / 256, 256>>>();                       // 1
  fill_kernel<<<E4, 256>>>(ei);                                       // 2

  // Layer 1: g_p = dinv .* (x@W1) ; g_d1 = dinv .* dropout(celu(dj*Σ + b1))
  proj_kernel<64, 32, 0, 1, -1, 0><<<(NN * 8 + 255) / 256, 256>>>(x, W1, nullptr, 0u, 0u);  // 3
  agg_kernel<1, 1, 0, 1><<<WB, 256>>>(b1, nullptr, DKEY1.x, DKEY1.y); // 4 (profiled)

  // Layer 2: g_p = dj*Σ(g_d1) ; g_d2 = dropout(celu(g_p@W2 + b2))
  agg_kernel<0, 0, 1, 0><<<WB, 256>>>(nullptr, nullptr, 0u, 0u);      // 5
  proj_kernel<32, 64, 1, 0, 0, 2><<<(NN * 16 + 255) / 256, 256>>>(nullptr, W2, b2,
                                                                  DKEY2.x, DKEY2.y);  // 6

  // Layer 3: g_p = dinv .* (g_d2@W3) ; out = celu(dj*Σ + b3)
  proj_kernel<64, 32, 0, 1, 2, 0><<<(NN * 8 + 255) / 256, 256>>>(nullptr, W3, nullptr, 0u, 0u);  // 7
  agg_kernel<2, 0, 0, -1><<<WB, 256>>>(b3, out, 0u, 0u);              // 8
}